// round 3
// baseline (speedup 1.0000x reference)
#include <cuda_runtime.h>

static constexpr int H    = 96;
static constexpr int PW   = 580;          // packed node-output width: 3*96 src + 3*96 dst + 4 attn scalars
static constexpr int NCG  = PW / 4;       // 145 float4 groups
static constexpr int NMAXC = 100000;

// ------------------------ device scratch (no allocs allowed) ------------------------
// float4-typed to guarantee 16B alignment for vector LDG/STG/red.v4
__device__ float4   g_W4[H * NCG];                     // packed weight [k][col/4]
__device__ float    g_C[3 * H];                        // per-type constant c_t
__device__ float4   g_node4[(size_t)NMAXC * NCG];      // per-node packed outputs
__device__ float4   g_attn[NMAXC];                     // (a_s0, a_d0, a_s1, a_d1)
__device__ float4   g_acc4[(size_t)3 * NMAXC * (H/4)]; // scatter accumulators
__device__ float    g_den[3 * NMAXC];                  // softmax denominators / mean counts

// ------------------------ K_prep: pack weights ------------------------
__global__ void k_prep(const float* __restrict__ Wm0, const float* __restrict__ Wm1,
                       const float* __restrict__ Wm2,
                       const float* __restrict__ bm0, const float* __restrict__ bm1,
                       const float* __restrict__ bm2,
                       const float* __restrict__ ef0, const float* __restrict__ ef1,
                       const float* __restrict__ ef2,
                       const float* __restrict__ Wn0, const float* __restrict__ Wa0,
                       const float* __restrict__ Wn1, const float* __restrict__ Wa1) {
    const float* Wm[3] = {Wm0, Wm1, Wm2};
    const float* bm[3] = {bm0, bm1, bm2};
    const float* ef[3] = {ef0, ef1, ef2};
    int tid = blockIdx.x * blockDim.x + threadIdx.x;
    int stride = blockDim.x * gridDim.x;
    float* g_W = (float*)g_W4;

    for (int idx = tid; idx < H * PW; idx += stride) {
        int k = idx / PW, c = idx % PW;
        float v;
        if (c < 288) {                     // src-half rows [0:96) of Wm_t
            int t = c / 96, j = c % 96;
            v = Wm[t][k * 96 + j];
        } else if (c < 576) {              // dst-half rows [96:192) of Wm_t
            int t = (c - 288) / 96, j = (c - 288) % 96;
            v = Wm[t][(96 + k) * 96 + j];
        } else {                           // folded attention vectors Wn @ Wa-half
            int which = c - 576;           // 0:a_s0 1:a_d0 2:a_s1 3:a_d1
            const float* Wn = (which < 2) ? Wn0 : Wn1;
            const float* Wa = (which < 2) ? Wa0 : Wa1;
            int off = (which & 1) * 32;
            float s = 0.f;
            #pragma unroll
            for (int j = 0; j < 32; j++) s += Wn[k * 32 + j] * Wa[off + j];
            v = s;
        }
        g_W[idx] = v;
    }
    // c_t[j] = bm_t[j] + ef_t . Wm_t[192:208, j]
    for (int idx = tid; idx < 3 * H; idx += stride) {
        int t = idx / 96, j = idx % 96;
        float s = bm[t][j];
        #pragma unroll
        for (int i = 0; i < 16; i++) s += ef[t][i] * Wm[t][(192 + i) * 96 + j];
        g_C[idx] = s;
    }
}

// ------------------------ K_init: zero accumulators ------------------------
__global__ void k_init(int N) {
    int tid = blockIdx.x * blockDim.x + threadIdx.x;
    int stride = blockDim.x * gridDim.x;
    int accq = 3 * N * (H / 4);
    float4 z4 = make_float4(0.f, 0.f, 0.f, 0.f);
    for (int i = tid; i < accq; i += stride) g_acc4[i] = z4;
    for (int i = tid; i < 3 * N; i += stride) g_den[i] = 0.f;
}

// ------------------------ K_node: packed GEMM [N x 96] @ [96 x 580] ------------------------
__global__ void __launch_bounds__(256) k_node(const float* __restrict__ h, int N) {
    __shared__ __align__(16) float hs[32 * H];    // 12 KB tile
    int n0 = blockIdx.x * 32;
    int tid = threadIdx.x;

    for (int e = tid; e < 32 * H; e += 256) {
        size_t gi = (size_t)n0 * H + e;
        hs[e] = (gi < (size_t)N * H) ? h[gi] : 0.f;
    }
    __syncthreads();

    for (int o = tid; o < 32 * NCG; o += 256) {
        int n = o / NCG, cg = o % NCG;
        if (n0 + n >= N) continue;
        const float* hp = &hs[n * H];
        const float4* Wp = g_W4 + cg;              // row stride NCG float4s
        float4 acc = make_float4(0.f, 0.f, 0.f, 0.f);
        #pragma unroll
        for (int k = 0; k < H; k += 4) {
            float4 hk = *(const float4*)(hp + k);
            float4 w0 = Wp[(k + 0) * NCG];
            float4 w1 = Wp[(k + 1) * NCG];
            float4 w2 = Wp[(k + 2) * NCG];
            float4 w3 = Wp[(k + 3) * NCG];
            acc.x = fmaf(hk.x, w0.x, acc.x); acc.y = fmaf(hk.x, w0.y, acc.y);
            acc.z = fmaf(hk.x, w0.z, acc.z); acc.w = fmaf(hk.x, w0.w, acc.w);
            acc.x = fmaf(hk.y, w1.x, acc.x); acc.y = fmaf(hk.y, w1.y, acc.y);
            acc.z = fmaf(hk.y, w1.z, acc.z); acc.w = fmaf(hk.y, w1.w, acc.w);
            acc.x = fmaf(hk.z, w2.x, acc.x); acc.y = fmaf(hk.z, w2.y, acc.y);
            acc.z = fmaf(hk.z, w2.z, acc.z); acc.w = fmaf(hk.z, w2.w, acc.w);
            acc.x = fmaf(hk.w, w3.x, acc.x); acc.y = fmaf(hk.w, w3.y, acc.y);
            acc.z = fmaf(hk.w, w3.z, acc.z); acc.w = fmaf(hk.w, w3.w, acc.w);
        }
        g_node4[(size_t)(n0 + n) * NCG + cg] = acc;
        if (cg == 144) g_attn[n0 + n] = acc;       // cols 576..579 = attention scalars
    }
}

// ------------------------ K_scatter: warp per edge, inline softmax weight, vector red ------------------------
// No max-subtraction: scores are ~N(0,1) for this model (|s| < ~7), exp() is safe in fp32
// and exp(s)/sum(exp(s)) is algebraically identical to the max-shifted form.
__global__ void __launch_bounds__(256) k_scatter(
        const int* __restrict__ src0, const int* __restrict__ dst0,
        const int* __restrict__ src1, const int* __restrict__ dst1,
        const int* __restrict__ src2, const int* __restrict__ dst2,
        int E, int N) {
    int gw = (blockIdx.x * blockDim.x + threadIdx.x) >> 5;
    int lane = threadIdx.x & 31;
    if (gw >= 3 * E) return;
    int t, e;
    if (gw < E)          { t = 0; e = gw; }
    else if (gw < 2 * E) { t = 1; e = gw - E; }
    else                 { t = 2; e = gw - 2 * E; }

    int s = 0, d = 0;
    float w = 0.f;
    if (lane == 0) {
        const int* sp = (t == 0) ? src0 : (t == 1) ? src1 : src2;
        const int* dp = (t == 0) ? dst0 : (t == 1) ? dst1 : dst2;
        s = sp[e]; d = dp[e];
        if (t < 2) {
            float4 as = g_attn[s], ad = g_attn[d];
            float x = t ? (as.z + ad.w) : (as.x + ad.y);
            float sc = (x > 0.f) ? x : 0.01f * x;  // leaky_relu(0.01)
            w = __expf(sc);
        } else {
            w = 1.0f;
        }
        atomicAdd(&g_den[t * N + d], w);
    }
    s = __shfl_sync(0xffffffffu, s, 0);
    d = __shfl_sync(0xffffffffu, d, 0);
    w = __shfl_sync(0xffffffffu, w, 0);

    if (lane < 24) {                                // 24 * float4 = 96 floats (src-half column block t)
        float4 v = g_node4[(size_t)s * NCG + t * (H / 4) + lane];
        float4* a = &g_acc4[((size_t)t * N + d) * (H / 4) + lane];
        asm volatile("red.global.add.v4.f32 [%0], {%1,%2,%3,%4};"
                     :: "l"(a), "f"(v.x * w), "f"(v.y * w), "f"(v.z * w), "f"(v.w * w)
                     : "memory");
    }
}

// ------------------------ K_final: assemble messages + fused update GEMM [N x 384] @ [384 x 96] ------------------------
__global__ void __launch_bounds__(256) k_final(const float* __restrict__ h,
                                               const float* __restrict__ Wu,
                                               const float* __restrict__ bu,
                                               float* __restrict__ out, int N) {
    __shared__ __align__(16) float xs[32 * 384];    // 48 KB
    int n0 = blockIdx.x * 32;
    int tid = threadIdx.x;
    const float* g_node = (const float*)g_node4;
    const float* g_acc  = (const float*)g_acc4;

    for (int ep = tid; ep < 32 * 384; ep += 256) {
        int n = ep / 384, c = ep % 384;
        int gn = n0 + n;
        float v = 0.f;
        if (gn < N) {
            if (c < 96) {
                v = h[(size_t)gn * 96 + c];
            } else {
                int t = (c - 96) / 96, j = (c - 96) % 96;
                float den = g_den[t * N + gn];
                if (den > 0.f) {
                    float accv = g_acc[((size_t)t * N + gn) * H + j];
                    float pd   = g_node[(size_t)gn * PW + 288 + t * 96 + j];
                    v = accv / den + pd + g_C[t * 96 + j];
                }
            }
        }
        xs[n * 384 + c] = v;
    }
    __syncthreads();

    for (int o = tid; o < 32 * 24; o += 256) {
        int n = o / 24, cg = o % 24;
        if (n0 + n >= N) continue;
        const float* xp = &xs[n * 384];
        const float4* Wp = (const float4*)Wu + cg;  // row stride 24 float4s
        float4 acc = *((const float4*)bu + cg);
        #pragma unroll 8
        for (int k = 0; k < 384; k += 4) {
            float4 xk = *(const float4*)(xp + k);
            float4 w0 = Wp[(k + 0) * 24];
            float4 w1 = Wp[(k + 1) * 24];
            float4 w2 = Wp[(k + 2) * 24];
            float4 w3 = Wp[(k + 3) * 24];
            acc.x = fmaf(xk.x, w0.x, acc.x); acc.y = fmaf(xk.x, w0.y, acc.y);
            acc.z = fmaf(xk.x, w0.z, acc.z); acc.w = fmaf(xk.x, w0.w, acc.w);
            acc.x = fmaf(xk.y, w1.x, acc.x); acc.y = fmaf(xk.y, w1.y, acc.y);
            acc.z = fmaf(xk.y, w1.z, acc.z); acc.w = fmaf(xk.y, w1.w, acc.w);
            acc.x = fmaf(xk.z, w2.x, acc.x); acc.y = fmaf(xk.z, w2.y, acc.y);
            acc.z = fmaf(xk.z, w2.z, acc.z); acc.w = fmaf(xk.z, w2.w, acc.w);
            acc.x = fmaf(xk.w, w3.x, acc.x); acc.y = fmaf(xk.w, w3.y, acc.y);
            acc.z = fmaf(xk.w, w3.z, acc.z); acc.w = fmaf(xk.w, w3.w, acc.w);
        }
        acc.x = fmaxf(acc.x, 0.f); acc.y = fmaxf(acc.y, 0.f);
        acc.z = fmaxf(acc.z, 0.f); acc.w = fmaxf(acc.w, 0.f);
        ((float4*)out)[(size_t)(n0 + n) * 24 + cg] = acc;
    }
}

// ------------------------ launch ------------------------
extern "C" void kernel_launch(void* const* d_in, const int* in_sizes, int n_in,
                              void* d_out, int out_size) {
    const float* h    = (const float*)d_in[0];
    const int*   src0 = (const int*)d_in[1];
    const int*   dst0 = (const int*)d_in[2];
    const int*   src1 = (const int*)d_in[3];
    const int*   dst1 = (const int*)d_in[4];
    const int*   src2 = (const int*)d_in[5];
    const int*   dst2 = (const int*)d_in[6];
    const float* Wm0  = (const float*)d_in[7];
    const float* bm0  = (const float*)d_in[8];
    const float* ef0  = (const float*)d_in[9];
    const float* Wm1  = (const float*)d_in[10];
    const float* bm1  = (const float*)d_in[11];
    const float* ef1  = (const float*)d_in[12];
    const float* Wm2  = (const float*)d_in[13];
    const float* bm2  = (const float*)d_in[14];
    const float* ef2  = (const float*)d_in[15];
    const float* Wn0  = (const float*)d_in[16];
    const float* Wa0  = (const float*)d_in[17];
    const float* Wn1  = (const float*)d_in[18];
    const float* Wa1  = (const float*)d_in[19];
    const float* Wu   = (const float*)d_in[20];
    const float* bu   = (const float*)d_in[21];

    int N = in_sizes[0] / H;
    int E = in_sizes[1];

    k_prep<<<4, 256>>>(Wm0, Wm1, Wm2, bm0, bm1, bm2, ef0, ef1, ef2, Wn0, Wa0, Wn1, Wa1);
    k_init<<<1024, 256>>>(N);
    k_node<<<(N + 31) / 32, 256>>>(h, N);
    long warps = 3L * (long)E;
    k_scatter<<<(unsigned)((warps + 7) / 8), 256>>>(src0, dst0, src1, dst1, src2, dst2, E, N);
    k_final<<<(N + 31) / 32, 256>>>(h, Wu, bu, (float*)d_out, N);
}

// round 5
// speedup vs baseline: 1.8130x; 1.8130x over previous
#include <cuda_runtime.h>

static constexpr int H    = 96;
static constexpr int PW   = 580;          // packed node-output width: 3*96 src + 3*96 dst + 4 attn scalars
static constexpr int NCG  = PW / 4;       // 145 float4 groups
static constexpr int NMAXC = 100000;

// ------------------------ device scratch (no allocs allowed) ------------------------
__device__ float4   g_W4[H * NCG];                     // packed weight [k][col/4]
__device__ float    g_C[3 * H];                        // per-type constant c_t
__device__ float4   g_node4[(size_t)NMAXC * NCG];      // per-node packed outputs
__device__ float4   g_attn[NMAXC];                     // (a_s0, a_d0, a_s1, a_d1)
__device__ float4   g_acc4[(size_t)3 * NMAXC * (H/4)]; // scatter accumulators
__device__ float    g_den[3 * NMAXC];                  // softmax denominators / mean counts

// ------------------------ f32x2 helpers ------------------------
__device__ __forceinline__ void fma2(unsigned long long& c, unsigned long long a, unsigned long long b) {
    asm("fma.rn.f32x2 %0, %1, %2, %0;" : "+l"(c) : "l"(a), "l"(b));
}
__device__ __forceinline__ unsigned long long pk2(float x, float y) {
    unsigned long long r;
    asm("mov.b64 %0, {%1, %2};" : "=l"(r) : "f"(x), "f"(y));
    return r;
}
__device__ __forceinline__ void upk2(float& x, float& y, unsigned long long v) {
    asm("mov.b64 {%0, %1}, %2;" : "=f"(x), "=f"(y) : "l"(v));
}
__device__ __forceinline__ void ldg2x64(unsigned long long& a, unsigned long long& b, const void* p) {
    asm("ld.global.v2.u64 {%0, %1}, [%2];" : "=l"(a), "=l"(b) : "l"(p));
}
__device__ __forceinline__ void stg2x64(void* p, unsigned long long a, unsigned long long b) {
    asm("st.global.v2.u64 [%0], {%1, %2};" :: "l"(p), "l"(a), "l"(b) : "memory");
}

// ------------------------ K_prep: pack weights ------------------------
__global__ void k_prep(const float* __restrict__ Wm0, const float* __restrict__ Wm1,
                       const float* __restrict__ Wm2,
                       const float* __restrict__ bm0, const float* __restrict__ bm1,
                       const float* __restrict__ bm2,
                       const float* __restrict__ ef0, const float* __restrict__ ef1,
                       const float* __restrict__ ef2,
                       const float* __restrict__ Wn0, const float* __restrict__ Wa0,
                       const float* __restrict__ Wn1, const float* __restrict__ Wa1) {
    const float* Wm[3] = {Wm0, Wm1, Wm2};
    const float* bm[3] = {bm0, bm1, bm2};
    const float* ef[3] = {ef0, ef1, ef2};
    int tid = blockIdx.x * blockDim.x + threadIdx.x;
    int stride = blockDim.x * gridDim.x;
    float* g_W = (float*)g_W4;

    for (int idx = tid; idx < H * PW; idx += stride) {
        int k = idx / PW, c = idx % PW;
        float v;
        if (c < 288) {                     // src-half rows [0:96) of Wm_t
            int t = c / 96, j = c % 96;
            v = Wm[t][k * 96 + j];
        } else if (c < 576) {              // dst-half rows [96:192) of Wm_t
            int t = (c - 288) / 96, j = (c - 288) % 96;
            v = Wm[t][(96 + k) * 96 + j];
        } else {                           // folded attention vectors Wn @ Wa-half
            int which = c - 576;           // 0:a_s0 1:a_d0 2:a_s1 3:a_d1
            const float* Wn = (which < 2) ? Wn0 : Wn1;
            const float* Wa = (which < 2) ? Wa0 : Wa1;
            int off = (which & 1) * 32;
            float s = 0.f;
            #pragma unroll
            for (int j = 0; j < 32; j++) s += Wn[k * 32 + j] * Wa[off + j];
            v = s;
        }
        g_W[idx] = v;
    }
    // c_t[j] = bm_t[j] + ef_t . Wm_t[192:208, j]
    for (int idx = tid; idx < 3 * H; idx += stride) {
        int t = idx / 96, j = idx % 96;
        float s = bm[t][j];
        #pragma unroll
        for (int i = 0; i < 16; i++) s += ef[t][i] * Wm[t][(192 + i) * 96 + j];
        g_C[idx] = s;
    }
}

// ------------------------ K_init: zero accumulators ------------------------
__global__ void k_init(int N) {
    int tid = blockIdx.x * blockDim.x + threadIdx.x;
    int stride = blockDim.x * gridDim.x;
    int accq = 3 * N * (H / 4);
    float4 z4 = make_float4(0.f, 0.f, 0.f, 0.f);
    for (int i = tid; i < accq; i += stride) g_acc4[i] = z4;
    for (int i = tid; i < 3 * N; i += stride) g_den[i] = 0.f;
}

// ------------------------ K_node: packed GEMM [N x 96] @ [96 x 580] ------------------------
// Register-tiled: 8 nodes per thread per W column-group, f32x2 packed FMA.
// h tile pre-packed (h,h) in smem so the inner loop has zero packing movs.
static constexpr int TN = 64;              // node tile
__global__ void __launch_bounds__(256) k_node(const float* __restrict__ h, int N) {
    __shared__ unsigned long long hs2[TN * H];   // 64*96*8 = 49152 B (=48KB)
    int n0 = blockIdx.x * TN;
    int tid = threadIdx.x;

    // load tile: read float4, store packed (x,x),(y,y),(z,z),(w,w)
    for (int idx = tid; idx < TN * (H / 4); idx += 256) {   // 1536 float4
        int n = idx / (H / 4);
        int c4 = idx % (H / 4);
        float4 v = make_float4(0.f, 0.f, 0.f, 0.f);
        if (n0 + n < N) v = ((const float4*)h)[(size_t)(n0 + n) * (H / 4) + c4];
        int base = n * H + c4 * 4;
        hs2[base + 0] = pk2(v.x, v.x);
        hs2[base + 1] = pk2(v.y, v.y);
        hs2[base + 2] = pk2(v.z, v.z);
        hs2[base + 3] = pk2(v.w, v.w);
    }
    __syncthreads();

    for (int task = tid; task < NCG * (TN / 8); task += 256) {
        int cg = task % NCG;               // adjacent threads -> adjacent cg (coalesced W)
        int nb = (task / NCG) * 8;         // node sub-tile base
        const float4* Wp = g_W4 + cg;
        const unsigned long long* hp = &hs2[nb * H];

        unsigned long long a0[8], a1[8];
        #pragma unroll
        for (int i = 0; i < 8; i++) { a0[i] = 0ull; a1[i] = 0ull; }

        #pragma unroll 4
        for (int k = 0; k < H; k++) {
            unsigned long long w0, w1;
            ldg2x64(w0, w1, Wp + (size_t)k * NCG);
            #pragma unroll
            for (int i = 0; i < 8; i++) {
                unsigned long long hh = hp[i * H + k];   // LDS.64 broadcast
                fma2(a0[i], hh, w0);
                fma2(a1[i], hh, w1);
            }
        }

        #pragma unroll
        for (int i = 0; i < 8; i++) {
            int n = n0 + nb + i;
            if (n < N) {
                stg2x64(&g_node4[(size_t)n * NCG + cg], a0[i], a1[i]);
                if (cg == NCG - 1) stg2x64(&g_attn[n], a0[i], a1[i]);  // cols 576..579
            }
        }
    }
}

// ------------------------ K_scatter: warp per edge, inline softmax weight, vector red ------------------------
// No max-subtraction: scores are ~N(0,1) for this model, exp() safe in fp32;
// exp(s)/sum(exp(s)) is algebraically identical to the max-shifted form.
__global__ void __launch_bounds__(256) k_scatter(
        const int* __restrict__ src0, const int* __restrict__ dst0,
        const int* __restrict__ src1, const int* __restrict__ dst1,
        const int* __restrict__ src2, const int* __restrict__ dst2,
        int E, int N) {
    int gw = (blockIdx.x * blockDim.x + threadIdx.x) >> 5;
    int lane = threadIdx.x & 31;
    if (gw >= 3 * E) return;
    int t, e;
    if (gw < E)          { t = 0; e = gw; }
    else if (gw < 2 * E) { t = 1; e = gw - E; }
    else                 { t = 2; e = gw - 2 * E; }

    int s = 0, d = 0;
    float w = 0.f;
    if (lane == 0) {
        const int* sp = (t == 0) ? src0 : (t == 1) ? src1 : src2;
        const int* dp = (t == 0) ? dst0 : (t == 1) ? dst1 : dst2;
        s = sp[e]; d = dp[e];
        if (t < 2) {
            float4 as = g_attn[s], ad = g_attn[d];
            float x = t ? (as.z + ad.w) : (as.x + ad.y);
            float sc = (x > 0.f) ? x : 0.01f * x;  // leaky_relu(0.01)
            w = __expf(sc);
        } else {
            w = 1.0f;
        }
        atomicAdd(&g_den[t * N + d], w);
    }
    s = __shfl_sync(0xffffffffu, s, 0);
    d = __shfl_sync(0xffffffffu, d, 0);
    w = __shfl_sync(0xffffffffu, w, 0);

    if (lane < 24) {                                // 24 * float4 = 96 floats (src-half column block t)
        float4 v = g_node4[(size_t)s * NCG + t * (H / 4) + lane];
        float4* a = &g_acc4[((size_t)t * N + d) * (H / 4) + lane];
        asm volatile("red.global.add.v4.f32 [%0], {%1,%2,%3,%4};"
                     :: "l"(a), "f"(v.x * w), "f"(v.y * w), "f"(v.z * w), "f"(v.w * w)
                     : "memory");
    }
}

// ------------------------ K_final: assemble messages + fused update GEMM [N x 384] @ [384 x 96] ------------------------
// Register-tiled: 4 nodes per thread per W column-group (24 cg x 8 groups = 192 threads).
__global__ void __launch_bounds__(192) k_final(const float* __restrict__ h,
                                               const float* __restrict__ Wu,
                                               const float* __restrict__ bu,
                                               float* __restrict__ out, int N) {
    __shared__ __align__(16) float xs[32 * 384];    // 48 KB
    int n0 = blockIdx.x * 32;
    int tid = threadIdx.x;
    const float* g_node = (const float*)g_node4;
    const float* g_acc  = (const float*)g_acc4;

    for (int ep = tid; ep < 32 * 384; ep += 192) {
        int n = ep / 384, c = ep % 384;
        int gn = n0 + n;
        float v = 0.f;
        if (gn < N) {
            if (c < 96) {
                v = h[(size_t)gn * 96 + c];
            } else {
                int t = (c - 96) / 96, j = (c - 96) % 96;
                float den = g_den[t * N + gn];
                if (den > 0.f) {
                    float accv = g_acc[((size_t)t * N + gn) * H + j];
                    float pd   = g_node[(size_t)gn * PW + 288 + t * 96 + j];
                    v = accv / den + pd + g_C[t * 96 + j];
                }
            }
        }
        xs[n * 384 + c] = v;
    }
    __syncthreads();

    {
        int cg = tid % 24;                 // output float4 group (coalesced W)
        int nb = (tid / 24) * 4;           // 4 nodes per thread
        const float4* Wp = (const float4*)Wu + cg;
        float4 b = ((const float4*)bu)[cg];

        unsigned long long a0[4], a1[4];
        #pragma unroll
        for (int i = 0; i < 4; i++) { a0[i] = pk2(b.x, b.y); a1[i] = pk2(b.z, b.w); }

        #pragma unroll 4
        for (int k = 0; k < 384; k++) {
            unsigned long long w0, w1;
            ldg2x64(w0, w1, Wp + (size_t)k * 24);
            #pragma unroll
            for (int i = 0; i < 4; i++) {
                float hv = xs[(nb + i) * 384 + k];
                unsigned long long hh = pk2(hv, hv);
                fma2(a0[i], hh, w0);
                fma2(a1[i], hh, w1);
            }
        }

        #pragma unroll
        for (int i = 0; i < 4; i++) {
            int n = n0 + nb + i;
            if (n < N) {
                float4 r;
                upk2(r.x, r.y, a0[i]);
                upk2(r.z, r.w, a1[i]);
                r.x = fmaxf(r.x, 0.f); r.y = fmaxf(r.y, 0.f);
                r.z = fmaxf(r.z, 0.f); r.w = fmaxf(r.w, 0.f);
                ((float4*)out)[(size_t)n * 24 + cg] = r;
            }
        }
    }
}

// ------------------------ launch ------------------------
extern "C" void kernel_launch(void* const* d_in, const int* in_sizes, int n_in,
                              void* d_out, int out_size) {
    const float* h    = (const float*)d_in[0];
    const int*   src0 = (const int*)d_in[1];
    const int*   dst0 = (const int*)d_in[2];
    const int*   src1 = (const int*)d_in[3];
    const int*   dst1 = (const int*)d_in[4];
    const int*   src2 = (const int*)d_in[5];
    const int*   dst2 = (const int*)d_in[6];
    const float* Wm0  = (const float*)d_in[7];
    const float* bm0  = (const float*)d_in[8];
    const float* ef0  = (const float*)d_in[9];
    const float* Wm1  = (const float*)d_in[10];
    const float* bm1  = (const float*)d_in[11];
    const float* ef1  = (const float*)d_in[12];
    const float* Wm2  = (const float*)d_in[13];
    const float* bm2  = (const float*)d_in[14];
    const float* ef2  = (const float*)d_in[15];
    const float* Wn0  = (const float*)d_in[16];
    const float* Wa0  = (const float*)d_in[17];
    const float* Wn1  = (const float*)d_in[18];
    const float* Wa1  = (const float*)d_in[19];
    const float* Wu   = (const float*)d_in[20];
    const float* bu   = (const float*)d_in[21];

    int N = in_sizes[0] / H;
    int E = in_sizes[1];

    k_prep<<<4, 256>>>(Wm0, Wm1, Wm2, bm0, bm1, bm2, ef0, ef1, ef2, Wn0, Wa0, Wn1, Wa1);
    k_init<<<1024, 256>>>(N);
    k_node<<<(N + TN - 1) / TN, 256>>>(h, N);
    long warps = 3L * (long)E;
    k_scatter<<<(unsigned)((warps + 7) / 8), 256>>>(src0, dst0, src1, dst1, src2, dst2, E, N);
    k_final<<<(N + 31) / 32, 192>>>(h, Wu, bu, (float*)d_out, N);
}

// round 9
// speedup vs baseline: 1.9760x; 1.0899x over previous
#include <cuda_runtime.h>

static constexpr int H    = 96;
static constexpr int PW   = 580;          // packed node-output width: 3*96 src + 3*96 dst + 4 attn scalars
static constexpr int NCG  = PW / 4;       // 145 float4 groups
static constexpr int NMAXC = 100000;

// ------------------------ device scratch (no allocs allowed) ------------------------
__device__ float4   g_W4[H * NCG];                     // packed weight [k][col/4]
__device__ float    g_C[3 * H];                        // per-type constant c_t
__device__ float4   g_node4[(size_t)NMAXC * NCG];      // per-node packed outputs
__device__ float4   g_attn[NMAXC];                     // (a_s0, a_d0, a_s1, a_d1)
__device__ float4   g_acc4[(size_t)3 * NMAXC * (H/4)]; // scatter accumulators
__device__ float    g_den[3 * NMAXC];                  // softmax denominators / mean counts

// ------------------------ f32x2 helpers ------------------------
__device__ __forceinline__ void fma2(unsigned long long& c, unsigned long long a, unsigned long long b) {
    asm("fma.rn.f32x2 %0, %1, %2, %0;" : "+l"(c) : "l"(a), "l"(b));
}
__device__ __forceinline__ unsigned long long pk2(float x, float y) {
    unsigned long long r;
    asm("mov.b64 %0, {%1, %2};" : "=l"(r) : "f"(x), "f"(y));
    return r;
}
__device__ __forceinline__ void upk2(float& x, float& y, unsigned long long v) {
    asm("mov.b64 {%0, %1}, %2;" : "=f"(x), "=f"(y) : "l"(v));
}
__device__ __forceinline__ void ldg2x64(unsigned long long& a, unsigned long long& b, const void* p) {
    asm("ld.global.v2.u64 {%0, %1}, [%2];" : "=l"(a), "=l"(b) : "l"(p));
}
__device__ __forceinline__ void stg2x64(void* p, unsigned long long a, unsigned long long b) {
    asm("st.global.v2.u64 [%0], {%1, %2};" :: "l"(p), "l"(a), "l"(b) : "memory");
}

// ------------------------ K_prep: pack weights ------------------------
__global__ void k_prep(const float* __restrict__ Wm0, const float* __restrict__ Wm1,
                       const float* __restrict__ Wm2,
                       const float* __restrict__ bm0, const float* __restrict__ bm1,
                       const float* __restrict__ bm2,
                       const float* __restrict__ ef0, const float* __restrict__ ef1,
                       const float* __restrict__ ef2,
                       const float* __restrict__ Wn0, const float* __restrict__ Wa0,
                       const float* __restrict__ Wn1, const float* __restrict__ Wa1) {
    const float* Wm[3] = {Wm0, Wm1, Wm2};
    const float* bm[3] = {bm0, bm1, bm2};
    const float* ef[3] = {ef0, ef1, ef2};
    int tid = blockIdx.x * blockDim.x + threadIdx.x;
    int stride = blockDim.x * gridDim.x;
    float* g_W = (float*)g_W4;

    for (int idx = tid; idx < H * PW; idx += stride) {
        int k = idx / PW, c = idx % PW;
        float v;
        if (c < 288) {                     // src-half rows [0:96) of Wm_t
            int t = c / 96, j = c % 96;
            v = Wm[t][k * 96 + j];
        } else if (c < 576) {              // dst-half rows [96:192) of Wm_t
            int t = (c - 288) / 96, j = (c - 288) % 96;
            v = Wm[t][(96 + k) * 96 + j];
        } else {                           // folded attention vectors Wn @ Wa-half
            int which = c - 576;           // 0:a_s0 1:a_d0 2:a_s1 3:a_d1
            const float* Wn = (which < 2) ? Wn0 : Wn1;
            const float* Wa = (which < 2) ? Wa0 : Wa1;
            int off = (which & 1) * 32;
            float s = 0.f;
            #pragma unroll
            for (int j = 0; j < 32; j++) s += Wn[k * 32 + j] * Wa[off + j];
            v = s;
        }
        g_W[idx] = v;
    }
    // c_t[j] = bm_t[j] + ef_t . Wm_t[192:208, j]
    for (int idx = tid; idx < 3 * H; idx += stride) {
        int t = idx / 96, j = idx % 96;
        float s = bm[t][j];
        #pragma unroll
        for (int i = 0; i < 16; i++) s += ef[t][i] * Wm[t][(192 + i) * 96 + j];
        g_C[idx] = s;
    }
}

// ------------------------ K_init: zero accumulators ------------------------
__global__ void k_init(int N) {
    int tid = blockIdx.x * blockDim.x + threadIdx.x;
    int stride = blockDim.x * gridDim.x;
    int accq = 3 * N * (H / 4);
    float4 z4 = make_float4(0.f, 0.f, 0.f, 0.f);
    for (int i = tid; i < accq; i += stride) g_acc4[i] = z4;
    for (int i = tid; i < 3 * N; i += stride) g_den[i] = 0.f;
}

// ------------------------ K_node: packed GEMM [N x 96] @ [96 x 580] ------------------------
// Register-tiled: 8 nodes per thread per W column-group, f32x2 packed FMA.
static constexpr int TN = 64;              // node tile
__global__ void __launch_bounds__(256) k_node(const float* __restrict__ h, int N) {
    __shared__ unsigned long long hs2[TN * H];   // 48KB
    int n0 = blockIdx.x * TN;
    int tid = threadIdx.x;

    for (int idx = tid; idx < TN * (H / 4); idx += 256) {   // 1536 float4
        int n = idx / (H / 4);
        int c4 = idx % (H / 4);
        float4 v = make_float4(0.f, 0.f, 0.f, 0.f);
        if (n0 + n < N) v = ((const float4*)h)[(size_t)(n0 + n) * (H / 4) + c4];
        int base = n * H + c4 * 4;
        hs2[base + 0] = pk2(v.x, v.x);
        hs2[base + 1] = pk2(v.y, v.y);
        hs2[base + 2] = pk2(v.z, v.z);
        hs2[base + 3] = pk2(v.w, v.w);
    }
    __syncthreads();

    for (int task = tid; task < NCG * (TN / 8); task += 256) {
        int cg = task % NCG;               // adjacent threads -> adjacent cg (coalesced W)
        int nb = (task / NCG) * 8;         // node sub-tile base
        const float4* Wp = g_W4 + cg;
        const unsigned long long* hp = &hs2[nb * H];

        unsigned long long a0[8], a1[8];
        #pragma unroll
        for (int i = 0; i < 8; i++) { a0[i] = 0ull; a1[i] = 0ull; }

        #pragma unroll 4
        for (int k = 0; k < H; k++) {
            unsigned long long w0, w1;
            ldg2x64(w0, w1, Wp + (size_t)k * NCG);
            #pragma unroll
            for (int i = 0; i < 8; i++) {
                unsigned long long hh = hp[i * H + k];   // LDS.64 broadcast
                fma2(a0[i], hh, w0);
                fma2(a1[i], hh, w1);
            }
        }

        #pragma unroll
        for (int i = 0; i < 8; i++) {
            int n = n0 + nb + i;
            if (n < N) {
                stg2x64(&g_node4[(size_t)n * NCG + cg], a0[i], a1[i]);
                if (cg == NCG - 1) stg2x64(&g_attn[n], a0[i], a1[i]);  // cols 576..579
            }
        }
    }
}

// ------------------------ K_scatter: 4 edges per warp, batched-MLP gather/red ------------------------
// No max-subtraction: scores ~N(0,1), exp() safe in fp32; exp(s)/sum(exp(s)) identical to shifted form.
__global__ void __launch_bounds__(256) k_scatter(
        const int* __restrict__ src0, const int* __restrict__ dst0,
        const int* __restrict__ src1, const int* __restrict__ dst1,
        const int* __restrict__ src2, const int* __restrict__ dst2,
        int E, int N) {
    const unsigned FULL = 0xffffffffu;
    int gw   = (blockIdx.x * blockDim.x + threadIdx.x) >> 5;
    int lane = threadIdx.x & 31;
    int wpt  = (E + 3) >> 2;               // warps per edge type
    if (gw >= 3 * wpt) return;
    int t  = gw / wpt;
    int e0 = (gw - t * wpt) * 4;

    const int* sp = (t == 0) ? src0 : (t == 1) ? src1 : src2;
    const int* dp = (t == 0) ? dst0 : (t == 1) ? dst1 : dst2;

    // lanes 0-3 load src[e0+lane], lanes 4-7 load dst[e0+lane-4]  (MLP=8)
    int idx = 0;
    if (lane < 8) {
        int e = e0 + (lane & 3);
        if (e < E) idx = (lane < 4) ? sp[e] : dp[e];
    }
    int dsh = __shfl_down_sync(FULL, idx, 4);   // lanes 0-3: their edge's dst

    // lanes 0-3: per-edge weight (2 random 16B loads each -> warp MLP=8) + den atomic
    float w = 1.f;
    if (lane < 4 && e0 + lane < E) {
        if (t < 2) {
            float4 as = g_attn[idx];
            float4 ad = g_attn[dsh];
            float x  = t ? (as.z + ad.w) : (as.x + ad.y);
            float sc = (x > 0.f) ? x : 0.01f * x;    // leaky_relu(0.01)
            w = __expf(sc);
        }
        atomicAdd(&g_den[t * N + dsh], w);
    }

    // batched gathers: 4 independent LDG.128 chains in flight
    float4 v[4];
    int    dj[4];
    float  wj[4];
    #pragma unroll
    for (int j = 0; j < 4; j++) {
        int s  = __shfl_sync(FULL, idx, j);
        dj[j]  = __shfl_sync(FULL, idx, 4 + j);
        wj[j]  = __shfl_sync(FULL, w, j);
        if (lane < 24 && e0 + j < E)
            v[j] = g_node4[(size_t)s * NCG + t * (H / 4) + lane];
    }
    #pragma unroll
    for (int j = 0; j < 4; j++) {
        if (lane < 24 && e0 + j < E) {
            float4* a = &g_acc4[((size_t)t * N + dj[j]) * (H / 4) + lane];
            float ww = wj[j];
            asm volatile("red.global.add.v4.f32 [%0], {%1,%2,%3,%4};"
                         :: "l"(a), "f"(v[j].x * ww), "f"(v[j].y * ww),
                            "f"(v[j].z * ww), "f"(v[j].w * ww)
                         : "memory");
        }
    }
}

// ------------------------ K_final: assemble messages + fused update GEMM [N x 384] @ [384 x 96] ------------------------
__global__ void __launch_bounds__(192) k_final(const float* __restrict__ h,
                                               const float* __restrict__ Wu,
                                               const float* __restrict__ bu,
                                               float* __restrict__ out, int N) {
    __shared__ __align__(16) float xs[32 * 384];    // 48 KB
    __shared__ float rden[32 * 3];
    int n0 = blockIdx.x * 32;
    int tid = threadIdx.x;
    const float* g_node = (const float*)g_node4;
    const float* g_acc  = (const float*)g_acc4;

    // stage reciprocals once per (node, type)
    if (tid < 96) {
        int n = tid / 3, t = tid % 3;
        float den = (n0 + n < N) ? g_den[t * N + n0 + n] : 0.f;
        rden[n * 3 + t] = (den > 0.f) ? 1.0f / den : 0.f;
    }
    __syncthreads();

    for (int ep = tid; ep < 32 * 384; ep += 192) {
        int n = ep / 384, c = ep % 384;
        int gn = n0 + n;
        float v = 0.f;
        if (gn < N) {
            if (c < 96) {
                v = h[(size_t)gn * 96 + c];
            } else {
                int t = (c - 96) / 96, j = (c - 96) % 96;
                float rd = rden[n * 3 + t];
                if (rd > 0.f) {
                    float accv = g_acc[((size_t)t * N + gn) * H + j];
                    float pd   = g_node[(size_t)gn * PW + 288 + t * 96 + j];
                    v = fmaf(accv, rd, pd + g_C[t * 96 + j]);
                }
            }
        }
        xs[n * 384 + c] = v;
    }
    __syncthreads();

    {
        int cg = tid % 24;                 // output float4 group (coalesced W)
        int nb = (tid / 24) * 4;           // 4 nodes per thread
        const float4* Wp = (const float4*)Wu + cg;
        float4 b = ((const float4*)bu)[cg];

        unsigned long long a0[4], a1[4];
        #pragma unroll
        for (int i = 0; i < 4; i++) { a0[i] = pk2(b.x, b.y); a1[i] = pk2(b.z, b.w); }

        #pragma unroll 4
        for (int k = 0; k < 384; k++) {
            unsigned long long w0, w1;
            ldg2x64(w0, w1, Wp + (size_t)k * 24);
            #pragma unroll
            for (int i = 0; i < 4; i++) {
                float hv = xs[(nb + i) * 384 + k];
                unsigned long long hh = pk2(hv, hv);
                fma2(a0[i], hh, w0);
                fma2(a1[i], hh, w1);
            }
        }

        #pragma unroll
        for (int i = 0; i < 4; i++) {
            int n = n0 + nb + i;
            if (n < N) {
                float4 r;
                upk2(r.x, r.y, a0[i]);
                upk2(r.z, r.w, a1[i]);
                r.x = fmaxf(r.x, 0.f); r.y = fmaxf(r.y, 0.f);
                r.z = fmaxf(r.z, 0.f); r.w = fmaxf(r.w, 0.f);
                ((float4*)out)[(size_t)n * 24 + cg] = r;
            }
        }
    }
}

// ------------------------ launch ------------------------
extern "C" void kernel_launch(void* const* d_in, const int* in_sizes, int n_in,
                              void* d_out, int out_size) {
    const float* h    = (const float*)d_in[0];
    const int*   src0 = (const int*)d_in[1];
    const int*   dst0 = (const int*)d_in[2];
    const int*   src1 = (const int*)d_in[3];
    const int*   dst1 = (const int*)d_in[4];
    const int*   src2 = (const int*)d_in[5];
    const int*   dst2 = (const int*)d_in[6];
    const float* Wm0  = (const float*)d_in[7];
    const float* bm0  = (const float*)d_in[8];
    const float* ef0  = (const float*)d_in[9];
    const float* Wm1  = (const float*)d_in[10];
    const float* bm1  = (const float*)d_in[11];
    const float* ef1  = (const float*)d_in[12];
    const float* Wm2  = (const float*)d_in[13];
    const float* bm2  = (const float*)d_in[14];
    const float* ef2  = (const float*)d_in[15];
    const float* Wn0  = (const float*)d_in[16];
    const float* Wa0  = (const float*)d_in[17];
    const float* Wn1  = (const float*)d_in[18];
    const float* Wa1  = (const float*)d_in[19];
    const float* Wu   = (const float*)d_in[20];
    const float* bu   = (const float*)d_in[21];

    int N = in_sizes[0] / H;
    int E = in_sizes[1];

    k_prep<<<48, 256>>>(Wm0, Wm1, Wm2, bm0, bm1, bm2, ef0, ef1, ef2, Wn0, Wa0, Wn1, Wa1);
    k_init<<<1024, 256>>>(N);
    k_node<<<(N + TN - 1) / TN, 256>>>(h, N);
    int wpt = (E + 3) / 4;
    long warps = 3L * wpt;
    k_scatter<<<(unsigned)((warps + 7) / 8), 256>>>(src0, dst0, src1, dst1, src2, dst2, E, N);
    k_final<<<(N + 31) / 32, 192>>>(h, Wu, bu, (float*)d_out, N);
}

// round 10
// speedup vs baseline: 2.3305x; 1.1794x over previous
#include <cuda_runtime.h>

static constexpr int H    = 96;
static constexpr int PW2  = 292;          // k_node packed width: 3*96 src + 4 attn scalars
static constexpr int NCG2 = PW2 / 4;      // 73 float4 groups
static constexpr int NSG  = H / 4;        // 24 float4 groups per type row
static constexpr int NMAXC = 100000;

// ------------------------ device scratch (no allocs allowed) ------------------------
__device__ float4   g_W2[H * NCG2];                    // packed node weight [k][col/4]
__device__ float    g_C[3 * H];                        // per-type constant c_t
__device__ __align__(128) float4 g_src4[(size_t)3 * NMAXC * NSG];  // src-half, 384B rows
__device__ float4   g_attn[NMAXC];                     // (a_s0, a_d0, a_s1, a_d1)
__device__ float4   g_acc4[(size_t)3 * NMAXC * NSG];   // scatter accumulators
__device__ float    g_den[3 * NMAXC];                  // softmax denominators / mean counts
__device__ float4   g_Wf[384 * NSG];                   // folded final weight [k][j/4]
__device__ float4   g_Mneg[3 * H * NSG];               // -(Wdst_t @ Wu_t), [t][k][j/4]

// ------------------------ f32x2 helpers ------------------------
__device__ __forceinline__ void fma2(unsigned long long& c, unsigned long long a, unsigned long long b) {
    asm("fma.rn.f32x2 %0, %1, %2, %0;" : "+l"(c) : "l"(a), "l"(b));
}
__device__ __forceinline__ unsigned long long pk2(float x, float y) {
    unsigned long long r;
    asm("mov.b64 %0, {%1, %2};" : "=l"(r) : "f"(x), "f"(y));
    return r;
}
__device__ __forceinline__ void upk2(float& x, float& y, unsigned long long v) {
    asm("mov.b64 {%0, %1}, %2;" : "=f"(x), "=f"(y) : "l"(v));
}
__device__ __forceinline__ void ldg2x64(unsigned long long& a, unsigned long long& b, const void* p) {
    asm("ld.global.v2.u64 {%0, %1}, [%2];" : "=l"(a), "=l"(b) : "l"(p));
}
__device__ __forceinline__ void stg2x64(void* p, unsigned long long a, unsigned long long b) {
    asm("st.global.v2.u64 [%0], {%1, %2};" :: "l"(p), "l"(a), "l"(b) : "memory");
}

// ------------------------ K_prep: pack weights + fold dst-half into final GEMM ------------------------
__global__ void k_prep(const float* __restrict__ Wm0, const float* __restrict__ Wm1,
                       const float* __restrict__ Wm2,
                       const float* __restrict__ bm0, const float* __restrict__ bm1,
                       const float* __restrict__ bm2,
                       const float* __restrict__ ef0, const float* __restrict__ ef1,
                       const float* __restrict__ ef2,
                       const float* __restrict__ Wn0, const float* __restrict__ Wa0,
                       const float* __restrict__ Wn1, const float* __restrict__ Wa1,
                       const float* __restrict__ Wu) {
    const float* Wm[3] = {Wm0, Wm1, Wm2};
    const float* bm[3] = {bm0, bm1, bm2};
    const float* ef[3] = {ef0, ef1, ef2};
    int tid = blockIdx.x * blockDim.x + threadIdx.x;
    int stride = blockDim.x * gridDim.x;

    // ---- W2: src halves + attention fold, [96 x 292] ----
    float* W2 = (float*)g_W2;
    for (int idx = tid; idx < H * PW2; idx += stride) {
        int k = idx / PW2, c = idx % PW2;
        float v;
        if (c < 288) {                     // src-half rows [0:96) of Wm_t
            int t = c / 96, j = c % 96;
            v = Wm[t][k * 96 + j];
        } else {                           // folded attention vectors Wn @ Wa-half
            int which = c - 288;           // 0:a_s0 1:a_d0 2:a_s1 3:a_d1
            const float* Wn = (which < 2) ? Wn0 : Wn1;
            const float* Wa = (which < 2) ? Wa0 : Wa1;
            int off = (which & 1) * 32;
            float s = 0.f;
            #pragma unroll
            for (int j = 0; j < 32; j++) s += Wn[k * 32 + j] * Wa[off + j];
            v = s;
        }
        W2[idx] = v;
    }
    // ---- c_t[j] = bm_t[j] + ef_t . Wm_t[192:208, j] ----
    for (int idx = tid; idx < 3 * H; idx += stride) {
        int t = idx / 96, j = idx % 96;
        float s = bm[t][j];
        #pragma unroll
        for (int i = 0; i < 16; i++) s += ef[t][i] * Wm[t][(192 + i) * 96 + j];
        g_C[idx] = s;
    }
    // ---- Wf[k][j]: k<96 -> Wu_h + sum_t Wdst_t@Wu_t ; k>=96 -> Wu row ----
    float* Wf = (float*)g_Wf;
    for (int idx = tid; idx < 384 * H; idx += stride) {
        int k = idx / 96, j = idx % 96;
        float v = Wu[k * 96 + j];
        if (k < 96) {
            #pragma unroll
            for (int t = 0; t < 3; t++) {
                const float* wm = Wm[t];
                float s = 0.f;
                for (int i = 0; i < 96; i++)
                    s += wm[(96 + k) * 96 + i] * Wu[(96 + 96 * t + i) * 96 + j];
                v += s;
            }
        }
        Wf[k * 96 + j] = v;
    }
    // ---- Mneg[t][k][j] = -(Wdst_t @ Wu_t)[k][j]  (empty-node correction) ----
    float* Mn = (float*)g_Mneg;
    for (int idx = tid; idx < 3 * H * H; idx += stride) {
        int t = idx / (96 * 96), r = idx % (96 * 96);
        int k = r / 96, j = r % 96;
        const float* wm = Wm[t];
        float s = 0.f;
        for (int i = 0; i < 96; i++)
            s += wm[(96 + k) * 96 + i] * Wu[(96 + 96 * t + i) * 96 + j];
        Mn[(t * 96 + k) * 96 + j] = -s;
    }
}

// ------------------------ K_init: zero accumulators ------------------------
__global__ void k_init(int N) {
    int tid = blockIdx.x * blockDim.x + threadIdx.x;
    int stride = blockDim.x * gridDim.x;
    int accq = 3 * N * NSG;
    float4 z4 = make_float4(0.f, 0.f, 0.f, 0.f);
    for (int i = tid; i < accq; i += stride) g_acc4[i] = z4;
    for (int i = tid; i < 3 * N; i += stride) g_den[i] = 0.f;
}

// ------------------------ K_node: packed GEMM [N x 96] @ [96 x 292] ------------------------
// Register-tiled: 8 nodes per thread per W column-group, f32x2 packed FMA.
static constexpr int TN = 64;              // node tile
__global__ void __launch_bounds__(256) k_node(const float* __restrict__ h, int N) {
    __shared__ unsigned long long hs2[TN * H];   // 48KB
    int n0 = blockIdx.x * TN;
    int tid = threadIdx.x;

    for (int idx = tid; idx < TN * (H / 4); idx += 256) {   // 1536 float4
        int n = idx / (H / 4);
        int c4 = idx % (H / 4);
        float4 v = make_float4(0.f, 0.f, 0.f, 0.f);
        if (n0 + n < N) v = ((const float4*)h)[(size_t)(n0 + n) * (H / 4) + c4];
        int base = n * H + c4 * 4;
        hs2[base + 0] = pk2(v.x, v.x);
        hs2[base + 1] = pk2(v.y, v.y);
        hs2[base + 2] = pk2(v.z, v.z);
        hs2[base + 3] = pk2(v.w, v.w);
    }
    __syncthreads();

    for (int task = tid; task < NCG2 * (TN / 8); task += 256) {
        int cg = task % NCG2;              // adjacent threads -> adjacent cg (coalesced W)
        int nb = (task / NCG2) * 8;        // node sub-tile base
        const float4* Wp = g_W2 + cg;
        const unsigned long long* hp = &hs2[nb * H];

        unsigned long long a0[8], a1[8];
        #pragma unroll
        for (int i = 0; i < 8; i++) { a0[i] = 0ull; a1[i] = 0ull; }

        #pragma unroll 4
        for (int k = 0; k < H; k++) {
            unsigned long long w0, w1;
            ldg2x64(w0, w1, Wp + (size_t)k * NCG2);
            #pragma unroll
            for (int i = 0; i < 8; i++) {
                unsigned long long hh = hp[i * H + k];   // LDS.64 broadcast
                fma2(a0[i], hh, w0);
                fma2(a1[i], hh, w1);
            }
        }

        if (cg < 72) {
            int t = cg / NSG, off = cg % NSG;
            #pragma unroll
            for (int i = 0; i < 8; i++) {
                int n = n0 + nb + i;
                if (n < N)
                    stg2x64(&g_src4[((size_t)t * N + n) * NSG + off], a0[i], a1[i]);
            }
        } else {                            // cg==72: attention scalars (cols 288-291)
            #pragma unroll
            for (int i = 0; i < 8; i++) {
                int n = n0 + nb + i;
                if (n < N) stg2x64(&g_attn[n], a0[i], a1[i]);
            }
        }
    }
}

// ------------------------ K_scatter: 4 edges per warp, batched-MLP gather/red ------------------------
// No max-subtraction: scores ~N(0,1), exp() safe in fp32; exp(s)/sum(exp(s)) identical to shifted form.
__global__ void __launch_bounds__(256) k_scatter(
        const int* __restrict__ src0, const int* __restrict__ dst0,
        const int* __restrict__ src1, const int* __restrict__ dst1,
        const int* __restrict__ src2, const int* __restrict__ dst2,
        int E, int N) {
    const unsigned FULL = 0xffffffffu;
    int gw   = (blockIdx.x * blockDim.x + threadIdx.x) >> 5;
    int lane = threadIdx.x & 31;
    int wpt  = (E + 3) >> 2;               // warps per edge type
    if (gw >= 3 * wpt) return;
    int t  = gw / wpt;
    int e0 = (gw - t * wpt) * 4;

    const int* sp = (t == 0) ? src0 : (t == 1) ? src1 : src2;
    const int* dp = (t == 0) ? dst0 : (t == 1) ? dst1 : dst2;
    const float4* sb = g_src4 + (size_t)t * N * NSG;   // 384B-aligned rows
    float4* ab = g_acc4 + (size_t)t * N * NSG;

    // lanes 0-3 load src[e0+lane], lanes 4-7 load dst[e0+lane-4]  (MLP=8)
    int idx = 0;
    if (lane < 8) {
        int e = e0 + (lane & 3);
        if (e < E) idx = (lane < 4) ? sp[e] : dp[e];
    }
    int dsh = __shfl_down_sync(FULL, idx, 4);   // lanes 0-3: their edge's dst

    // lanes 0-3: per-edge weight (2 random 16B loads each -> warp MLP=8) + den atomic
    float w = 1.f;
    if (lane < 4 && e0 + lane < E) {
        if (t < 2) {
            float4 as = g_attn[idx];
            float4 ad = g_attn[dsh];
            float x  = t ? (as.z + ad.w) : (as.x + ad.y);
            float sc = (x > 0.f) ? x : 0.01f * x;    // leaky_relu(0.01)
            w = __expf(sc);
        }
        atomicAdd(&g_den[t * N + dsh], w);
    }

    // batched gathers: 4 independent LDG.128 chains in flight
    float4 v[4];
    int    dj[4];
    float  wj[4];
    #pragma unroll
    for (int j = 0; j < 4; j++) {
        int s  = __shfl_sync(FULL, idx, j);
        dj[j]  = __shfl_sync(FULL, idx, 4 + j);
        wj[j]  = __shfl_sync(FULL, w, j);
        if (lane < 24 && e0 + j < E)
            v[j] = sb[(size_t)s * NSG + lane];
    }
    #pragma unroll
    for (int j = 0; j < 4; j++) {
        if (lane < 24 && e0 + j < E) {
            float4* a = &ab[(size_t)dj[j] * NSG + lane];
            float ww = wj[j];
            asm volatile("red.global.add.v4.f32 [%0], {%1,%2,%3,%4};"
                         :: "l"(a), "f"(v[j].x * ww), "f"(v[j].y * ww),
                            "f"(v[j].z * ww), "f"(v[j].w * ww)
                         : "memory");
        }
    }
}

// ------------------------ K_final: assemble + fused GEMM [N x 384] @ [384 x 96] (dst-half folded) ------------------------
__global__ void __launch_bounds__(192) k_final(const float* __restrict__ h,
                                               float* __restrict__ out, int N) {
    __shared__ __align__(16) float xs[32 * 384];    // 48 KB
    __shared__ float rden[32 * 3];
    int n0 = blockIdx.x * 32;
    int tid = threadIdx.x;
    const float* g_acc = (const float*)g_acc4;

    // stage reciprocals once per (node, type); 0 marks an empty mailbox
    if (tid < 96) {
        int n = tid / 3, t = tid % 3;
        float den = (n0 + n < N) ? g_den[t * N + n0 + n] : 1.f;
        rden[n * 3 + t] = (den > 0.f) ? 1.0f / den : 0.f;
    }
    __syncthreads();

    for (int ep = tid; ep < 32 * 384; ep += 192) {
        int n = ep / 384, c = ep % 384;
        int gn = n0 + n;
        float v = 0.f;
        if (gn < N) {
            if (c < 96) {
                v = h[(size_t)gn * 96 + c];
            } else {
                int t = (c - 96) / 96, j = (c - 96) % 96;
                float rd = rden[n * 3 + t];
                if (rd > 0.f) {
                    float accv = g_acc[(((size_t)t * N + gn) * NSG) * 4 + j];
                    v = fmaf(accv, rd, g_C[t * 96 + j]);
                }
            }
        }
        xs[n * 384 + c] = v;
    }
    __syncthreads();

    {
        int cg = tid % 24;                 // output float4 group (coalesced W)
        int nb = (tid / 24) * 4;           // 4 nodes per thread
        const float4* Wp = g_Wf + cg;

        unsigned long long a0[4], a1[4];
        #pragma unroll
        for (int i = 0; i < 4; i++) { a0[i] = 0ull; a1[i] = 0ull; }

        #pragma unroll 4
        for (int k = 0; k < 384; k++) {
            unsigned long long w0, w1;
            ldg2x64(w0, w1, Wp + (size_t)k * 24);
            #pragma unroll
            for (int i = 0; i < 4; i++) {
                float hv = xs[(nb + i) * 384 + k];
                unsigned long long hh = pk2(hv, hv);
                fma2(a0[i], hh, w0);
                fma2(a1[i], hh, w1);
            }
        }

        #pragma unroll
        for (int i = 0; i < 4; i++) {
            int n = n0 + nb + i;
            if (n < N) {
                // rare empty-node correction: subtract folded dst contribution h@M_t
                #pragma unroll
                for (int t = 0; t < 3; t++) {
                    if (rden[(nb + i) * 3 + t] == 0.f) {
                        const float4* Mp = g_Mneg + (size_t)t * H * 24 + cg;
                        for (int k = 0; k < H; k++) {
                            unsigned long long m0, m1;
                            ldg2x64(m0, m1, Mp + (size_t)k * 24);
                            float hv = xs[(nb + i) * 384 + k];
                            unsigned long long hh = pk2(hv, hv);
                            fma2(a0[i], hh, m0);
                            fma2(a1[i], hh, m1);
                        }
                    }
                }
                float4 r;
                upk2(r.x, r.y, a0[i]);
                upk2(r.z, r.w, a1[i]);
                r.x = fmaxf(r.x, 0.f); r.y = fmaxf(r.y, 0.f);
                r.z = fmaxf(r.z, 0.f); r.w = fmaxf(r.w, 0.f);
                ((float4*)out)[(size_t)n * 24 + cg] = r;
            }
        }
    }
}

// ------------------------ K_bias: add bias via Wf? (bias handled here: fold into out) ------------------------
// bu is added inside k_final via an extra K row? Simpler: initialize accumulators with bias.
// (k_final above starts acc at 0; bias is applied by k_prep folding bu into... NOT folded.)
// We instead pass bu to k_final through g_C? Cleanest: small fixup is wrong with relu.
// => handled by initializing a0/a1 with bu in k_final (see launch note below).

// ------------------------ launch ------------------------
extern "C" void kernel_launch(void* const* d_in, const int* in_sizes, int n_in,
                              void* d_out, int out_size);

// bias-aware final (redefines the accumulator init with bu)
__global__ void __launch_bounds__(192) k_final_b(const float* __restrict__ h,
                                                 const float* __restrict__ bu,
                                                 float* __restrict__ out, int N) {
    __shared__ __align__(16) float xs[32 * 384];
    __shared__ float rden[32 * 3];
    int n0 = blockIdx.x * 32;
    int tid = threadIdx.x;
    const float* g_acc = (const float*)g_acc4;

    if (tid < 96) {
        int n = tid / 3, t = tid % 3;
        float den = (n0 + n < N) ? g_den[t * N + n0 + n] : 1.f;
        rden[n * 3 + t] = (den > 0.f) ? 1.0f / den : 0.f;
    }
    __syncthreads();

    for (int ep = tid; ep < 32 * 384; ep += 192) {
        int n = ep / 384, c = ep % 384;
        int gn = n0 + n;
        float v = 0.f;
        if (gn < N) {
            if (c < 96) {
                v = h[(size_t)gn * 96 + c];
            } else {
                int t = (c - 96) / 96, j = (c - 96) % 96;
                float rd = rden[n * 3 + t];
                if (rd > 0.f) {
                    float accv = g_acc[((size_t)t * N + gn) * H + j];
                    v = fmaf(accv, rd, g_C[t * 96 + j]);
                }
            }
        }
        xs[n * 384 + c] = v;
    }
    __syncthreads();

    {
        int cg = tid % 24;
        int nb = (tid / 24) * 4;
        const float4* Wp = g_Wf + cg;
        float4 b = ((const float4*)bu)[cg];

        unsigned long long a0[4], a1[4];
        #pragma unroll
        for (int i = 0; i < 4; i++) { a0[i] = pk2(b.x, b.y); a1[i] = pk2(b.z, b.w); }

        #pragma unroll 4
        for (int k = 0; k < 384; k++) {
            unsigned long long w0, w1;
            ldg2x64(w0, w1, Wp + (size_t)k * 24);
            #pragma unroll
            for (int i = 0; i < 4; i++) {
                float hv = xs[(nb + i) * 384 + k];
                unsigned long long hh = pk2(hv, hv);
                fma2(a0[i], hh, w0);
                fma2(a1[i], hh, w1);
            }
        }

        #pragma unroll
        for (int i = 0; i < 4; i++) {
            int n = n0 + nb + i;
            if (n < N) {
                #pragma unroll
                for (int t = 0; t < 3; t++) {
                    if (rden[(nb + i) * 3 + t] == 0.f) {
                        const float4* Mp = g_Mneg + (size_t)t * H * 24 + cg;
                        for (int k = 0; k < H; k++) {
                            unsigned long long m0, m1;
                            ldg2x64(m0, m1, Mp + (size_t)k * 24);
                            float hv = xs[(nb + i) * 384 + k];
                            unsigned long long hh = pk2(hv, hv);
                            fma2(a0[i], hh, m0);
                            fma2(a1[i], hh, m1);
                        }
                    }
                }
                float4 r;
                upk2(r.x, r.y, a0[i]);
                upk2(r.z, r.w, a1[i]);
                r.x = fmaxf(r.x, 0.f); r.y = fmaxf(r.y, 0.f);
                r.z = fmaxf(r.z, 0.f); r.w = fmaxf(r.w, 0.f);
                ((float4*)out)[(size_t)n * 24 + cg] = r;
            }
        }
    }
}

extern "C" void kernel_launch(void* const* d_in, const int* in_sizes, int n_in,
                              void* d_out, int out_size) {
    const float* h    = (const float*)d_in[0];
    const int*   src0 = (const int*)d_in[1];
    const int*   dst0 = (const int*)d_in[2];
    const int*   src1 = (const int*)d_in[3];
    const int*   dst1 = (const int*)d_in[4];
    const int*   src2 = (const int*)d_in[5];
    const int*   dst2 = (const int*)d_in[6];
    const float* Wm0  = (const float*)d_in[7];
    const float* bm0  = (const float*)d_in[8];
    const float* ef0  = (const float*)d_in[9];
    const float* Wm1  = (const float*)d_in[10];
    const float* bm1  = (const float*)d_in[11];
    const float* ef1  = (const float*)d_in[12];
    const float* Wm2  = (const float*)d_in[13];
    const float* bm2  = (const float*)d_in[14];
    const float* ef2  = (const float*)d_in[15];
    const float* Wn0  = (const float*)d_in[16];
    const float* Wa0  = (const float*)d_in[17];
    const float* Wn1  = (const float*)d_in[18];
    const float* Wa1  = (const float*)d_in[19];
    const float* Wu   = (const float*)d_in[20];
    const float* bu   = (const float*)d_in[21];

    int N = in_sizes[0] / H;
    int E = in_sizes[1];

    k_prep<<<96, 256>>>(Wm0, Wm1, Wm2, bm0, bm1, bm2, ef0, ef1, ef2,
                        Wn0, Wa0, Wn1, Wa1, Wu);
    k_init<<<1024, 256>>>(N);
    k_node<<<(N + TN - 1) / TN, 256>>>(h, N);
    int wpt = (E + 3) / 4;
    long warps = 3L * wpt;
    k_scatter<<<(unsigned)((warps + 7) / 8), 256>>>(src0, dst0, src1, dst1, src2, dst2, E, N);
    k_final_b<<<(N + 31) / 32, 192>>>(h, bu, (float*)d_out, N);
}